// round 1
// baseline (speedup 1.0000x reference)
#include <cuda_runtime.h>
#include <cuda_bf16.h>

#define NH 10     // hidden size
#define NT 5      // tasks
#define NS 10     // steps

__device__ __forceinline__ float sigmoidf_(float x) {
    return 1.0f / (1.0f + __expf(-x));
}

// Decode a 10-element boolean mask whose storage dtype is unknown
// (float32 / int32 / packed uint8). The 32-bit word patterns are mutually
// distinguishable: float {0x0, 0x3F800000}, int {0x0, 0x1}, packed bools
// produce words with nonzero upper bytes. Deterministic per input.
__device__ void decode_mask10(const void* p, int* out) {
    const unsigned int* w = (const unsigned int*)p;
    bool isF = true, isI = true;
    #pragma unroll
    for (int i = 0; i < 10; i++) {
        unsigned int v = w[i];
        if (v != 0u && v != 0x3F800000u) isF = false;
        if (v > 1u) isI = false;
    }
    if (isF) {
        const float* f = (const float*)p;
        for (int i = 0; i < 10; i++) out[i] = (f[i] != 0.0f);
    } else if (isI) {
        const int* ii = (const int*)p;
        for (int i = 0; i < 10; i++) out[i] = ii[i];
    } else {
        const unsigned char* b = (const unsigned char*)p;
        for (int i = 0; i < 10; i++) out[i] = (b[i] != 0);
    }
}

__global__ void __launch_bounds__(192, 1)
rnnae_kernel(const float* __restrict__ omega,
             const float* __restrict__ noise,
             const void*  __restrict__ go1_raw,
             const void*  __restrict__ go2_raw,
             const float* __restrict__ W_ih,   // [40,2]
             const float* __restrict__ W_hh,   // [40,10]
             const float* __restrict__ b_ih,   // [40]
             const float* __restrict__ b_hh,   // [40]
             const float* __restrict__ w1,     // [20,10]
             const float* __restrict__ b1,     // [20]
             const float* __restrict__ w2,     // [20,20]
             const float* __restrict__ b2,     // [20]
             const float* __restrict__ w3,     // [1,20]
             const float* __restrict__ b3,     // [1]
             float* __restrict__ out)
{
    __shared__ float sWih[80];
    __shared__ float sWhh[400];
    __shared__ float sB[40];     // b_ih + b_hh
    __shared__ float sW1[200];
    __shared__ float sB1[20];
    __shared__ float sW2[400];
    __shared__ float sB2[20];
    __shared__ float sW3[20];
    __shared__ float sB3;
    __shared__ float sOmega[NT];
    __shared__ float sAh[NT][NS];
    __shared__ float sErr[NT];
    __shared__ int   sM1[10], sM2[10];

    const int tid = threadIdx.x;
    const int nthr = blockDim.x;

    // ---- cooperative load of all parameters into shared ----
    for (int i = tid; i < 80;  i += nthr) sWih[i] = W_ih[i];
    for (int i = tid; i < 400; i += nthr) sWhh[i] = W_hh[i];
    for (int i = tid; i < 40;  i += nthr) sB[i]   = b_ih[i] + b_hh[i];
    for (int i = tid; i < 200; i += nthr) sW1[i]  = w1[i];
    for (int i = tid; i < 20;  i += nthr) sB1[i]  = b1[i];
    for (int i = tid; i < 400; i += nthr) sW2[i]  = w2[i];
    for (int i = tid; i < 20;  i += nthr) sB2[i]  = b2[i];
    for (int i = tid; i < 20;  i += nthr) sW3[i]  = w3[i];
    for (int i = tid; i < NT;  i += nthr) sOmega[i] = omega[i];
    if (tid == 0) {
        sB3 = b3[0];
        decode_mask10(go1_raw, sM1);
        decode_mask10(go2_raw, sM2);
    }
    __syncthreads();

    // ---- precompute human action ah[t][s] ----
    for (int i = tid; i < NT * NS; i += nthr) {
        int t = i / NS, st = i % NS;
        float om = sOmega[t];
        bool g1 = (fabsf(om - 0.4f) < 1e-3f) || (fabsf(om - 0.8f) < 1e-3f);
        float scale = g1 ? 0.2f : 0.4f;
        int tm = g1 ? sM1[st] : sM2[st];
        sAh[t][st] = (tm ? (om - 0.6f) / scale : 0.0f) + noise[i];
    }
    __syncthreads();

    // ---- one warp per task; state in registers; shfl-only comms ----
    const int warp = tid >> 5;
    const int lane = tid & 31;
    const unsigned FULL = 0xffffffffu;

    if (warp < NT) {
        const int j = (lane < NH) ? lane : 0;   // hidden index this lane owns
        const int m = (lane < 20) ? lane : 0;   // MLP index this lane owns
        const float om = sOmega[warp];

        float s = 0.0f, c = 0.0f, h = 0.0f, err = 0.0f;

        // hoist per-lane weights into registers
        float wih_i0 = sWih[2*j],        wih_i1 = sWih[2*j+1];
        float wih_f0 = sWih[2*(10+j)],   wih_f1 = sWih[2*(10+j)+1];
        float wih_g0 = sWih[2*(20+j)],   wih_g1 = sWih[2*(20+j)+1];
        float wih_o0 = sWih[2*(30+j)],   wih_o1 = sWih[2*(30+j)+1];
        float bi = sB[j], bf = sB[10+j], bg = sB[20+j], bo = sB[30+j];
        float whh_i[NH], whh_f[NH], whh_g[NH], whh_o[NH];
        float rw1[NH], rw2[20];
        #pragma unroll
        for (int k = 0; k < NH; k++) {
            whh_i[k] = sWhh[j*NH + k];
            whh_f[k] = sWhh[(10+j)*NH + k];
            whh_g[k] = sWhh[(20+j)*NH + k];
            whh_o[k] = sWhh[(30+j)*NH + k];
            rw1[k]   = sW1[m*NH + k];
        }
        #pragma unroll
        for (int k = 0; k < 20; k++) rw2[k] = sW2[m*20 + k];
        float rb1 = sB1[m], rb2 = sB2[m], rw3 = sW3[m], rb3 = sB3;

        #pragma unroll 1
        for (int t = 0; t < NS; t++) {
            float ah = sAh[warp][t];

            // gather previous h (lives in lanes 0..9)
            float hh[NH];
            #pragma unroll
            for (int k = 0; k < NH; k++) hh[k] = __shfl_sync(FULL, h, k);

            float gi = fmaf(s, wih_i0, fmaf(ah, wih_i1, bi));
            float gf = fmaf(s, wih_f0, fmaf(ah, wih_f1, bf));
            float gg = fmaf(s, wih_g0, fmaf(ah, wih_g1, bg));
            float go = fmaf(s, wih_o0, fmaf(ah, wih_o1, bo));
            #pragma unroll
            for (int k = 0; k < NH; k++) {
                gi = fmaf(hh[k], whh_i[k], gi);
                gf = fmaf(hh[k], whh_f[k], gf);
                gg = fmaf(hh[k], whh_g[k], gg);
                go = fmaf(hh[k], whh_o[k], go);
            }
            gi = sigmoidf_(gi);
            gf = sigmoidf_(gf);
            gg = tanhf(gg);
            go = sigmoidf_(go);
            c = fmaf(gf, c, gi * gg);
            h = go * tanhf(c);

            // gather new h
            #pragma unroll
            for (int k = 0; k < NH; k++) hh[k] = __shfl_sync(FULL, h, k);

            // layer 1: h1[m] = relu(sum_k h[k] * w1[m,k] + b1[m])
            float h1 = rb1;
            #pragma unroll
            for (int k = 0; k < NH; k++) h1 = fmaf(hh[k], rw1[k], h1);
            h1 = fmaxf(h1, 0.0f);

            // gather h1 (lanes 0..19)
            float g1v[20];
            #pragma unroll
            for (int k = 0; k < 20; k++) g1v[k] = __shfl_sync(FULL, h1, k);

            // layer 2
            float h2 = rb2;
            #pragma unroll
            for (int k = 0; k < 20; k++) h2 = fmaf(g1v[k], rw2[k], h2);
            h2 = fmaxf(h2, 0.0f);

            // output: ar = sum_m h2[m]*w3[m] + b3  (butterfly reduce)
            float p = (lane < 20) ? h2 * rw3 : 0.0f;
            #pragma unroll
            for (int off = 16; off > 0; off >>= 1)
                p += __shfl_xor_sync(FULL, p, off);
            float ar = p + rb3;

            s += ar;
            float d = s - om;
            err = fmaf(d, d, err);
        }
        if (lane == 0) sErr[warp] = err;
    }
    __syncthreads();

    if (tid == 0) {
        float q = 0.0f;
        #pragma unroll
        for (int i = 0; i < NT; i++) q += sErr[i];
        out[0] = q;
    }
}

extern "C" void kernel_launch(void* const* d_in, const int* in_sizes, int n_in,
                              void* d_out, int out_size) {
    const float* omega = (const float*)d_in[0];
    const float* noise = (const float*)d_in[1];
    const void*  go1   = (const void*)d_in[2];
    const void*  go2   = (const void*)d_in[3];
    const float* W_ih  = (const float*)d_in[4];
    const float* W_hh  = (const float*)d_in[5];
    const float* b_ih  = (const float*)d_in[6];
    const float* b_hh  = (const float*)d_in[7];
    const float* w1    = (const float*)d_in[8];
    const float* b1    = (const float*)d_in[9];
    const float* w2    = (const float*)d_in[10];
    const float* b2    = (const float*)d_in[11];
    const float* w3    = (const float*)d_in[12];
    const float* b3    = (const float*)d_in[13];
    float* out = (float*)d_out;

    rnnae_kernel<<<1, 192>>>(omega, noise, go1, go2, W_ih, W_hh, b_ih, b_hh,
                             w1, b1, w2, b2, w3, b3, out);
}

// round 2
// speedup vs baseline: 1.8986x; 1.8986x over previous
#include <cuda_runtime.h>
#include <cuda_bf16.h>

#define NH 10     // hidden size
#define NT 5      // tasks
#define NS 10     // steps
#define FULLM 0xffffffffu

// fast sigmoid: 1/(1+exp(-x)); __expf = EX2, __fdividef = RCP-based.
// exp(-x)=inf for x<-88 -> rcp(inf)=0 -> returns 0 (correct limit).
__device__ __forceinline__ float fsig(float x) {
    float e = __expf(-x);
    return __fdividef(1.0f, 1.0f + e);
}
// fast tanh: 1 - 2/(exp(2x)+1). Robust at both saturation ends:
// exp->inf gives 1-0=1; exp->0 gives 1-2=-1.
__device__ __forceinline__ float ftanh(float x) {
    float e = __expf(2.0f * x);
    return 1.0f - __fdividef(2.0f, e + 1.0f);
}

// Decode 10-element boolean mask of unknown storage dtype
// (float32 / int32 / packed uint8). Word patterns are mutually
// distinguishable; deterministic per input.
__device__ void decode_mask10(const void* p, int* out) {
    const unsigned int* w = (const unsigned int*)p;
    bool isF = true, isI = true;
    #pragma unroll
    for (int i = 0; i < 10; i++) {
        unsigned int v = w[i];
        if (v != 0u && v != 0x3F800000u) isF = false;
        if (v > 1u) isI = false;
    }
    if (isF) {
        const float* f = (const float*)p;
        for (int i = 0; i < 10; i++) out[i] = (f[i] != 0.0f);
    } else if (isI) {
        const int* ii = (const int*)p;
        for (int i = 0; i < 10; i++) out[i] = ii[i];
    } else {
        const unsigned char* b = (const unsigned char*)p;
        for (int i = 0; i < 10; i++) out[i] = (b[i] != 0);
    }
}

__global__ void __launch_bounds__(160, 1)
rnnae_kernel(const float* __restrict__ omega,
             const float* __restrict__ noise,
             const void*  __restrict__ go1_raw,
             const void*  __restrict__ go2_raw,
             const float* __restrict__ W_ih,   // [40,2]
             const float* __restrict__ W_hh,   // [40,10]
             const float* __restrict__ b_ih,   // [40]
             const float* __restrict__ b_hh,   // [40]
             const float* __restrict__ w1,     // [20,10]
             const float* __restrict__ b1,     // [20]
             const float* __restrict__ w2,     // [20,20]
             const float* __restrict__ b2,     // [20]
             const float* __restrict__ w3,     // [1,20]
             const float* __restrict__ b3,     // [1]
             float* __restrict__ out)
{
    __shared__ float sWih[80];
    __shared__ float sWhh[400];
    __shared__ float sB[40];     // b_ih + b_hh
    __shared__ float sW1[200];
    __shared__ float sB1[20];
    __shared__ float sW2[400];
    __shared__ float sB2[20];
    __shared__ float sW3[20];
    __shared__ float sB3s[1];
    __shared__ int   sM1[10], sM2[10];
    __shared__ float sErr[NT];

    const int tid = threadIdx.x;

    // ---- cooperative parameter staging ----
    for (int i = tid; i < 80;  i += 160) sWih[i] = W_ih[i];
    for (int i = tid; i < 400; i += 160) sWhh[i] = W_hh[i];
    for (int i = tid; i < 40;  i += 160) sB[i]   = b_ih[i] + b_hh[i];
    for (int i = tid; i < 200; i += 160) sW1[i]  = w1[i];
    for (int i = tid; i < 20;  i += 160) sB1[i]  = b1[i];
    for (int i = tid; i < 400; i += 160) sW2[i]  = w2[i];
    for (int i = tid; i < 20;  i += 160) sB2[i]  = b2[i];
    for (int i = tid; i < 20;  i += 160) sW3[i]  = w3[i];
    if (tid == 0) {
        sB3s[0] = b3[0];
        decode_mask10(go1_raw, sM1);
        decode_mask10(go2_raw, sM2);
    }
    __syncthreads();

    const int warp = tid >> 5;
    const int lane = tid & 31;
    const int j = (lane < NH) ? lane : 0;   // hidden index owned by this lane
    const int m = (lane < 20) ? lane : 0;   // MLP index owned by this lane

    const float om = omega[warp];

    // ---- per-lane redundant precompute of human actions (10 regs) ----
    float ahr[NS];
    {
        bool g1 = (fabsf(om - 0.4f) < 1e-3f) || (fabsf(om - 0.8f) < 1e-3f);
        float scale = g1 ? 0.2f : 0.4f;
        float base = (om - 0.6f) / scale;
        #pragma unroll
        for (int t = 0; t < NS; t++) {
            int tm = g1 ? sM1[t] : sM2[t];
            ahr[t] = (tm ? base : 0.0f) + noise[warp * NS + t];
        }
    }

    // ---- hoist per-lane weights into registers ----
    float wih_i0 = sWih[2*j],        wih_i1 = sWih[2*j+1];
    float wih_f0 = sWih[2*(10+j)],   wih_f1 = sWih[2*(10+j)+1];
    float wih_g0 = sWih[2*(20+j)],   wih_g1 = sWih[2*(20+j)+1];
    float wih_o0 = sWih[2*(30+j)],   wih_o1 = sWih[2*(30+j)+1];
    float bi = sB[j], bf = sB[10+j], bg = sB[20+j], bo = sB[30+j];
    float whh_i[NH], whh_f[NH], whh_g[NH], whh_o[NH], rw1[NH];
    #pragma unroll
    for (int k = 0; k < NH; k++) {
        whh_i[k] = sWhh[j*NH + k];
        whh_f[k] = sWhh[(10+j)*NH + k];
        whh_g[k] = sWhh[(20+j)*NH + k];
        whh_o[k] = sWhh[(30+j)*NH + k];
        rw1[k]   = sW1[m*NH + k];
    }
    float rw2[20], rw3[20];
    #pragma unroll
    for (int k = 0; k < 20; k++) {
        rw2[k] = sW2[m*20 + k];
        rw3[k] = sW3[k];          // ALL w3 values in every lane (redundant dot)
    }
    float rb1 = sB1[m], rb2 = sB2[m], rb3 = sB3s[0];

    // ---- rollout: all state in registers, shfl-only comms, full unroll ----
    float s = 0.0f, c = 0.0f, err = 0.0f;
    float hh[NH];
    #pragma unroll
    for (int k = 0; k < NH; k++) hh[k] = 0.0f;

    #pragma unroll
    for (int t = 0; t < NS; t++) {
        float ah = ahr[t];

        // gates (2 accumulators per gate; s joins via a single late FMA,
        // letting the h-path of this step overlap the MLP tail of step t-1)
        float gia = fmaf(ah, wih_i1, bi), gib = 0.0f;
        float gfa = fmaf(ah, wih_f1, bf), gfb = 0.0f;
        float gga = fmaf(ah, wih_g1, bg), ggb = 0.0f;
        float goa = fmaf(ah, wih_o1, bo), gob = 0.0f;
        #pragma unroll
        for (int k = 0; k < 5; k++) {
            gia = fmaf(hh[k], whh_i[k], gia);  gib = fmaf(hh[k+5], whh_i[k+5], gib);
            gfa = fmaf(hh[k], whh_f[k], gfa);  gfb = fmaf(hh[k+5], whh_f[k+5], gfb);
            gga = fmaf(hh[k], whh_g[k], gga);  ggb = fmaf(hh[k+5], whh_g[k+5], ggb);
            goa = fmaf(hh[k], whh_o[k], goa);  gob = fmaf(hh[k+5], whh_o[k+5], gob);
        }
        float gi = fsig (fmaf(s, wih_i0, gia + gib));
        float gf = fsig (fmaf(s, wih_f0, gfa + gfb));
        float gg = ftanh(fmaf(s, wih_g0, gga + ggb));
        float go = fsig (fmaf(s, wih_o0, goa + gob));
        c = fmaf(gf, c, gi * gg);
        float h = go * ftanh(c);

        // gather h (single gather per step)
        #pragma unroll
        for (int k = 0; k < NH; k++) hh[k] = __shfl_sync(FULLM, h, k);

        // layer 1 (lane m owns h1[m]); 2 accumulators
        float h1a = rb1, h1b = 0.0f;
        #pragma unroll
        for (int k = 0; k < 5; k++) {
            h1a = fmaf(hh[k], rw1[k], h1a);
            h1b = fmaf(hh[k+5], rw1[k+5], h1b);
        }
        float h1 = fmaxf(h1a + h1b, 0.0f);

        float g1v[20];
        #pragma unroll
        for (int k = 0; k < 20; k++) g1v[k] = __shfl_sync(FULLM, h1, k);

        // layer 2; 4 accumulators
        float h2a = rb2, h2b = 0.0f, h2c = 0.0f, h2d = 0.0f;
        #pragma unroll
        for (int k = 0; k < 5; k++) {
            h2a = fmaf(g1v[k],    rw2[k],    h2a);
            h2b = fmaf(g1v[k+5],  rw2[k+5],  h2b);
            h2c = fmaf(g1v[k+10], rw2[k+10], h2c);
            h2d = fmaf(g1v[k+15], rw2[k+15], h2d);
        }
        float h2 = fmaxf((h2a + h2b) + (h2c + h2d), 0.0f);

        // gather h2, then every lane computes ar redundantly (4-acc tree)
        float g2v[20];
        #pragma unroll
        for (int k = 0; k < 20; k++) g2v[k] = __shfl_sync(FULLM, h2, k);

        float ra = rb3, rb = 0.0f, rc = 0.0f, rd = 0.0f;
        #pragma unroll
        for (int k = 0; k < 5; k++) {
            ra = fmaf(g2v[k],    rw3[k],    ra);
            rb = fmaf(g2v[k+5],  rw3[k+5],  rb);
            rc = fmaf(g2v[k+10], rw3[k+10], rc);
            rd = fmaf(g2v[k+15], rw3[k+15], rd);
        }
        float ar = (ra + rb) + (rc + rd);

        s += ar;                     // every lane tracks s -> no broadcast
        float d = s - om;
        err = fmaf(d, d, err);
    }

    if (lane == 0) sErr[warp] = err;
    __syncthreads();
    if (tid == 0) {
        out[0] = ((sErr[0] + sErr[1]) + (sErr[2] + sErr[3])) + sErr[4];
    }
}

extern "C" void kernel_launch(void* const* d_in, const int* in_sizes, int n_in,
                              void* d_out, int out_size) {
    const float* omega = (const float*)d_in[0];
    const float* noise = (const float*)d_in[1];
    const void*  go1   = (const void*)d_in[2];
    const void*  go2   = (const void*)d_in[3];
    const float* W_ih  = (const float*)d_in[4];
    const float* W_hh  = (const float*)d_in[5];
    const float* b_ih  = (const float*)d_in[6];
    const float* b_hh  = (const float*)d_in[7];
    const float* w1    = (const float*)d_in[8];
    const float* b1    = (const float*)d_in[9];
    const float* w2    = (const float*)d_in[10];
    const float* b2    = (const float*)d_in[11];
    const float* w3    = (const float*)d_in[12];
    const float* b3    = (const float*)d_in[13];
    float* out = (float*)d_out;

    rnnae_kernel<<<1, 160>>>(omega, noise, go1, go2, W_ih, W_hh, b_ih, b_hh,
                             w1, b1, w2, b2, w3, b3, out);
}

// round 3
// speedup vs baseline: 2.0927x; 1.1022x over previous
#include <cuda_runtime.h>
#include <cuda_bf16.h>

#define NH 10
#define NT 5
#define NS 10
#define FULLM 0xffffffffu

// MUFU.TANH (sm_75+): single 16-cycle instruction.
__device__ __forceinline__ float mtanh(float x) {
    float y;
    asm("tanh.approx.f32 %0, %1;" : "=f"(y) : "f"(x));
    return y;
}
// sigmoid(x) = 0.5*tanh(x/2) + 0.5
__device__ __forceinline__ float fsig(float x) {
    return fmaf(0.5f, mtanh(0.5f * x), 0.5f);
}

// Per-lane redundant decode of a 10-element bool mask of unknown storage
// dtype (float32 / int32 / packed uint8). Pure ALU after 10 broadcast loads.
__device__ __forceinline__ void decode_mask10(const unsigned int* w, int* out) {
    bool isF = true, isI = true;
    #pragma unroll
    for (int i = 0; i < 10; i++) {
        unsigned int v = w[i];
        if (v != 0u && v != 0x3F800000u) isF = false;
        if (v > 1u) isI = false;
    }
    if (isF || isI) {
        #pragma unroll
        for (int i = 0; i < 10; i++) out[i] = (w[i] != 0u);
    } else {
        const unsigned char* b = (const unsigned char*)w;
        #pragma unroll
        for (int i = 0; i < 10; i++) out[i] = (b[i] != 0);
    }
}

__global__ void __launch_bounds__(160, 1)
rnnae_kernel(const float* __restrict__ omega,
             const float* __restrict__ noise,
             const void*  __restrict__ go1_raw,
             const void*  __restrict__ go2_raw,
             const float* __restrict__ W_ih,   // [40,2]
             const float* __restrict__ W_hh,   // [40,10]
             const float* __restrict__ b_ih,   // [40]
             const float* __restrict__ b_hh,   // [40]
             const float* __restrict__ w1,     // [20,10]
             const float* __restrict__ b1,     // [20]
             const float* __restrict__ w2,     // [20,20]
             const float* __restrict__ b2,     // [20]
             const float* __restrict__ w3,     // [1,20]
             const float* __restrict__ b3,     // [1]
             float* __restrict__ out)
{
    __shared__ float sErr[NT];

    const int tid  = threadIdx.x;
    const int warp = tid >> 5;
    const int lane = tid & 31;
    const int j = (lane < NH) ? lane : 0;   // hidden index owned by this lane
    const int m = (lane < 20) ? lane : 0;   // MLP index owned by this lane

    // ================= direct global -> register load (one MLP wave) ======
    // LSTM input weights (rows j, 10+j, 20+j, 30+j)
    float wih_i0 = W_ih[2*j],        wih_i1 = W_ih[2*j+1];
    float wih_f0 = W_ih[2*(10+j)],   wih_f1 = W_ih[2*(10+j)+1];
    float wih_g0 = W_ih[2*(20+j)],   wih_g1 = W_ih[2*(20+j)+1];
    float wih_o0 = W_ih[2*(30+j)],   wih_o1 = W_ih[2*(30+j)+1];
    float bi = b_ih[j]    + b_hh[j];
    float bf = b_ih[10+j] + b_hh[10+j];
    float bg = b_ih[20+j] + b_hh[20+j];
    float bo = b_ih[30+j] + b_hh[30+j];

    float whh_i[NH], whh_f[NH], whh_g[NH], whh_o[NH], rw1[NH];
    #pragma unroll
    for (int k = 0; k < NH; k++) {
        whh_i[k] = W_hh[j*NH + k];
        whh_f[k] = W_hh[(10+j)*NH + k];
        whh_g[k] = W_hh[(20+j)*NH + k];
        whh_o[k] = W_hh[(30+j)*NH + k];
        rw1[k]   = w1[m*NH + k];
    }
    float rw2[20], rw3[20];
    #pragma unroll
    for (int k = 0; k < 20; k++) {
        rw2[k] = w2[m*20 + k];
        rw3[k] = w3[k];
    }
    float rb1 = b1[m], rb2 = b2[m], rb3 = b3[0];

    const float om = omega[warp];

    int m1[10], m2[10];
    decode_mask10((const unsigned int*)go1_raw, m1);
    decode_mask10((const unsigned int*)go2_raw, m2);

    // human actions, per-lane registers
    float ahr[NS];
    {
        bool g1 = (fabsf(om - 0.4f) < 1e-3f) || (fabsf(om - 0.8f) < 1e-3f);
        float scale = g1 ? 0.2f : 0.4f;
        float base = (om - 0.6f) / scale;
        #pragma unroll
        for (int t = 0; t < NS; t++) {
            int tm = g1 ? m1[t] : m2[t];
            ahr[t] = (tm ? base : 0.0f) + noise[warp * NS + t];
        }
    }

    // ================= rollout: registers + shfl only ======================
    float s = 0.0f, c = 0.0f, err = 0.0f;
    float hh[NH];
    #pragma unroll
    for (int k = 0; k < NH; k++) hh[k] = 0.0f;

    #pragma unroll
    for (int t = 0; t < NS; t++) {
        float ah = ahr[t];

        // gates: h-part first (2 accumulators each), s joins via one late FMA
        float gia = fmaf(ah, wih_i1, bi), gib = 0.0f;
        float gfa = fmaf(ah, wih_f1, bf), gfb = 0.0f;
        float gga = fmaf(ah, wih_g1, bg), ggb = 0.0f;
        float goa = fmaf(ah, wih_o1, bo), gob = 0.0f;
        #pragma unroll
        for (int k = 0; k < 5; k++) {
            gia = fmaf(hh[k], whh_i[k], gia);  gib = fmaf(hh[k+5], whh_i[k+5], gib);
            gfa = fmaf(hh[k], whh_f[k], gfa);  gfb = fmaf(hh[k+5], whh_f[k+5], gfb);
            gga = fmaf(hh[k], whh_g[k], gga);  ggb = fmaf(hh[k+5], whh_g[k+5], ggb);
            goa = fmaf(hh[k], whh_o[k], goa);  gob = fmaf(hh[k+5], whh_o[k+5], gob);
        }
        float gi = fsig (fmaf(s, wih_i0, gia + gib));
        float gf = fsig (fmaf(s, wih_f0, gfa + gfb));
        float gg = mtanh(fmaf(s, wih_g0, gga + ggb));
        float go = fsig (fmaf(s, wih_o0, goa + gob));
        c = fmaf(gf, c, gi * gg);
        float h = go * mtanh(c);

        // gather h
        #pragma unroll
        for (int k = 0; k < NH; k++) hh[k] = __shfl_sync(FULLM, h, k);

        // layer 1
        float h1a = rb1, h1b = 0.0f;
        #pragma unroll
        for (int k = 0; k < 5; k++) {
            h1a = fmaf(hh[k],   rw1[k],   h1a);
            h1b = fmaf(hh[k+5], rw1[k+5], h1b);
        }
        float h1 = fmaxf(h1a + h1b, 0.0f);

        float g1v[20];
        #pragma unroll
        for (int k = 0; k < 20; k++) g1v[k] = __shfl_sync(FULLM, h1, k);

        // layer 2
        float h2a = rb2, h2b = 0.0f, h2c = 0.0f, h2d = 0.0f;
        #pragma unroll
        for (int k = 0; k < 5; k++) {
            h2a = fmaf(g1v[k],    rw2[k],    h2a);
            h2b = fmaf(g1v[k+5],  rw2[k+5],  h2b);
            h2c = fmaf(g1v[k+10], rw2[k+10], h2c);
            h2d = fmaf(g1v[k+15], rw2[k+15], h2d);
        }
        float h2 = fmaxf((h2a + h2b) + (h2c + h2d), 0.0f);

        // gather h2; every lane computes ar redundantly
        float g2v[20];
        #pragma unroll
        for (int k = 0; k < 20; k++) g2v[k] = __shfl_sync(FULLM, h2, k);

        float ra = rb3, rb = 0.0f, rc = 0.0f, rd = 0.0f;
        #pragma unroll
        for (int k = 0; k < 5; k++) {
            ra = fmaf(g2v[k],    rw3[k],    ra);
            rb = fmaf(g2v[k+5],  rw3[k+5],  rb);
            rc = fmaf(g2v[k+10], rw3[k+10], rc);
            rd = fmaf(g2v[k+15], rw3[k+15], rd);
        }
        float ar = (ra + rb) + (rc + rd);

        s += ar;
        float d = s - om;
        err = fmaf(d, d, err);
    }

    if (lane == 0) sErr[warp] = err;
    __syncthreads();
    if (tid == 0) {
        out[0] = ((sErr[0] + sErr[1]) + (sErr[2] + sErr[3])) + sErr[4];
    }
}

extern "C" void kernel_launch(void* const* d_in, const int* in_sizes, int n_in,
                              void* d_out, int out_size) {
    const float* omega = (const float*)d_in[0];
    const float* noise = (const float*)d_in[1];
    const void*  go1   = (const void*)d_in[2];
    const void*  go2   = (const void*)d_in[3];
    const float* W_ih  = (const float*)d_in[4];
    const float* W_hh  = (const float*)d_in[5];
    const float* b_ih  = (const float*)d_in[6];
    const float* b_hh  = (const float*)d_in[7];
    const float* w1    = (const float*)d_in[8];
    const float* b1    = (const float*)d_in[9];
    const float* w2    = (const float*)d_in[10];
    const float* b2    = (const float*)d_in[11];
    const float* w3    = (const float*)d_in[12];
    const float* b3    = (const float*)d_in[13];
    float* out = (float*)d_out;

    rnnae_kernel<<<1, 160>>>(omega, noise, go1, go2, W_ih, W_hh, b_ih, b_hh,
                             w1, b1, w2, b2, w3, b3, out);
}